// round 8
// baseline (speedup 1.0000x reference)
#include <cuda_runtime.h>
#include <cuda_bf16.h>
#include <cstdint>

// Problem constants
#define BB 4
#define TT 2048
#define CC 1024
#define HH 16
#define DD 64
#define M_ROWS (BB * TT)          // 8192
#define N_QKV  (3 * CC)           // 3072

// Scratch (device globals — allocation-free)
__device__ float g_qkv[(size_t)M_ROWS * N_QKV];       // [B*T, 3C] (tf32-rounded)
__device__ float g_xp[(size_t)M_ROWS * CC];           // x, permuted A-tiles
__device__ float g_yp[(size_t)M_ROWS * CC];           // attention out, permuted A-tiles
__device__ float g_wqkvp[(size_t)CC * N_QKV];         // w_qkv, permuted B-tiles
__device__ float g_wprojp[(size_t)CC * CC];           // w_proj, permuted B-tiles

// ---------------------------------------------------------------------------
// Helpers
// ---------------------------------------------------------------------------
__device__ __forceinline__ unsigned f2tf32(float x) {
    unsigned r;
    asm("cvt.rna.tf32.f32 %0, %1;" : "=r"(r) : "f"(x));
    return r;
}
__device__ __forceinline__ float rnd_tf32(float x) {
    return __uint_as_float(f2tf32(x));
}
__device__ __forceinline__ float exp2a(float x) {
    float r;
    asm("ex2.approx.ftz.f32 %0, %1;" : "=f"(r) : "f"(x));
    return r;
}
__device__ __forceinline__ void mma_tf32(float* c, const unsigned* a, const unsigned* b) {
    asm volatile(
        "mma.sync.aligned.m16n8k8.row.col.f32.tf32.tf32.f32 "
        "{%0,%1,%2,%3}, {%4,%5,%6,%7}, {%8,%9}, {%0,%1,%2,%3};"
        : "+f"(c[0]), "+f"(c[1]), "+f"(c[2]), "+f"(c[3])
        : "r"(a[0]), "r"(a[1]), "r"(a[2]), "r"(a[3]),
          "r"(b[0]), "r"(b[1]));
}
__device__ __forceinline__ uint32_t smem_u32(const void* p) {
    uint32_t a;
    asm("{ .reg .u64 t; cvta.to.shared.u64 t, %1; cvt.u32.u64 %0, t; }" : "=r"(a) : "l"(p));
    return a;
}
__device__ __forceinline__ void cp16(uint32_t s, const void* g) {
    asm volatile("cp.async.cg.shared.global [%0], [%1], 16;" :: "r"(s), "l"(g));
}
__device__ __forceinline__ void cp_commit() {
    asm volatile("cp.async.commit_group;" ::: "memory");
}

// ---------------------------------------------------------------------------
// Prep: permute A (row-major [M][K] fp32) into GEMM A-tile layout, tf32-rounded.
// Tile (mb, kb) word w: row=w>>4, rem=w&15, q=rem>>2, t=rem&3,
//   s=(row^(row>>2))&3, k=(t<<2)|(q^s)  -> value in[(mb*128+row)*K + kb*16+k]
// ---------------------------------------------------------------------------
__global__ __launch_bounds__(256)
void permute_a_kernel(const float* __restrict__ in, float* __restrict__ out, int K, int nTot)
{
    int idx = blockIdx.x * 256 + threadIdx.x;
    if (idx >= nTot) return;
    const int nk = K >> 4;
    int tile = idx >> 11, w = idx & 2047;
    int mb = tile / nk, kb = tile - mb * nk;
    int row = w >> 4, rem = w & 15;
    int q = rem >> 2, t = rem & 3;
    int s = (row ^ (row >> 2)) & 3;
    int k = (t << 2) | (q ^ s);
    out[idx] = rnd_tf32(in[(size_t)(mb * 128 + row) * K + kb * 16 + k]);
}

// ---------------------------------------------------------------------------
// Prep: permute B (row-major [K][N] fp32) into GEMM B-tile layout, tf32-rounded.
// Tile (nb, kb) word w: k=w>>7, p=w&127, n=(p&15)*8+(p>>4)
//   -> value in[(kb*16+k)*N + nb*128+n]
// ---------------------------------------------------------------------------
__global__ __launch_bounds__(256)
void permute_b_kernel(const float* __restrict__ in, float* __restrict__ out, int N, int K, int nTot)
{
    int idx = blockIdx.x * 256 + threadIdx.x;
    if (idx >= nTot) return;
    const int nk = K >> 4;
    int tile = idx >> 11, w = idx & 2047;
    int nb = tile / nk, kb = tile - nb * nk;
    int k = w >> 7, p = w & 127;
    int n = (p & 15) * 8 + (p >> 4);
    out[idx] = rnd_tf32(in[(size_t)(kb * 16 + k) * N + nb * 128 + n]);
}

// ---------------------------------------------------------------------------
// Pipelined TF32 mma.sync GEMM:  C[M,N] = A @ B + bias.
// A/B pre-permuted tile layouts; 4-stage cp.async; 128x128x16 block; 8 warps.
// MMA ordering: all k8=0 MMAs, then all k8=1 MMAs (acc reuse gap = 16).
// ---------------------------------------------------------------------------
#define GSM_BYTES 66560

__device__ __forceinline__ void gemm_load_stage(uint32_t sb, const float* Atile,
                                                const float* Btile, int s, int kb, int tid)
{
    const float* Ab = Atile + (size_t)kb * 2048;
    const float* Bb = Btile + (size_t)kb * 2048;
    const uint32_t as_ = sb + s * 8192;
    const uint32_t bs_ = sb + 32768 + s * 8448;
    cp16(as_ + tid * 16, Ab + tid * 4);
    cp16(as_ + (tid + 256) * 16, Ab + (tid + 256) * 4);
    const int c0 = tid, c1 = tid + 256;
    cp16(bs_ + (c0 >> 5) * 528 + (c0 & 31) * 16, Bb + c0 * 4);
    cp16(bs_ + (c1 >> 5) * 528 + (c1 & 31) * 16, Bb + c1 * 4);
    cp_commit();
}

template <bool ROUND>
__global__ __launch_bounds__(256, 2)
void gemm_pipe(const float* __restrict__ Ap, const float* __restrict__ Bp,
               const float* __restrict__ bias, float* __restrict__ C,
               int N, int K)
{
    extern __shared__ char smem[];
    const uint32_t sb = smem_u32(smem);
    const int tid  = threadIdx.x;
    const int warp = tid >> 5;
    const int lane = tid & 31;
    const int lr = lane >> 2;
    const int lc = lane & 3;
    const int wm = (warp >> 2) * 64;
    const int wn = (warp & 3) * 32;
    const int wn8 = wn >> 3;
    const int nk = K >> 4;

    const float* Atile = Ap + (size_t)blockIdx.y * nk * 2048;
    const float* Btile = Bp + (size_t)blockIdx.x * nk * 2048;

    // Fragment LDS word offsets (verified layout)
    int aRd[4][2];
    #pragma unroll
    for (int mt = 0; mt < 4; mt++) {
        int rm = wm + mt * 16 + lr;
        int r8 = rm + 8;
        aRd[mt][0] = rm * 16 + 4 * (lc ^ ((rm ^ (rm >> 2)) & 3));
        aRd[mt][1] = r8 * 16 + 4 * (lc ^ ((r8 ^ (r8 >> 2)) & 3));
    }
    const int bRd = lr * 16 + wn8;

    float acc[4][4][4];
    #pragma unroll
    for (int i = 0; i < 4; i++)
        #pragma unroll
        for (int j = 0; j < 4; j++)
            #pragma unroll
            for (int r = 0; r < 4; r++) acc[i][j][r] = 0.0f;

    // Prologue: stages 0..2
    gemm_load_stage(sb, Atile, Btile, 0, 0, tid);
    gemm_load_stage(sb, Atile, Btile, 1, 1, tid);
    gemm_load_stage(sb, Atile, Btile, 2, 2, tid);

    for (int i = 0; i < nk; i++) {
        if (i + 3 <= nk)
            asm volatile("cp.async.wait_group 2;" ::: "memory");
        else
            asm volatile("cp.async.wait_group 0;" ::: "memory");
        __syncthreads();

        if (i + 3 < nk)
            gemm_load_stage(sb, Atile, Btile, (i + 3) & 3, i + 3, tid);

        const unsigned* asb = (const unsigned*)(smem + (size_t)(i & 3) * 8192);
        const unsigned* bsb = (const unsigned*)(smem + 32768 + (size_t)(i & 3) * 8448);

        uint4 b00 = *(const uint4*)&bsb[(lc)      * 132 + bRd];
        uint4 b01 = *(const uint4*)&bsb[(lc + 4)  * 132 + bRd];
        uint4 b10 = *(const uint4*)&bsb[(lc + 8)  * 132 + bRd];
        uint4 b11 = *(const uint4*)&bsb[(lc + 12) * 132 + bRd];

        uint4 alo[4], ahi[4];
        #pragma unroll
        for (int mt = 0; mt < 4; mt++) {
            alo[mt] = *(const uint4*)&asb[aRd[mt][0]];
            ahi[mt] = *(const uint4*)&asb[aRd[mt][1]];
        }

        // k8 = 0: 16 MMAs (each acc touched once)
        #pragma unroll
        for (int mt = 0; mt < 4; mt++) {
            unsigned af[4] = { alo[mt].x, ahi[mt].x, alo[mt].y, ahi[mt].y };
            unsigned bf[2];
            bf[0] = b00.x; bf[1] = b01.x; mma_tf32(acc[mt][0], af, bf);
            bf[0] = b00.y; bf[1] = b01.y; mma_tf32(acc[mt][1], af, bf);
            bf[0] = b00.z; bf[1] = b01.z; mma_tf32(acc[mt][2], af, bf);
            bf[0] = b00.w; bf[1] = b01.w; mma_tf32(acc[mt][3], af, bf);
        }
        // k8 = 1: 16 MMAs (acc reuse gap = 16)
        #pragma unroll
        for (int mt = 0; mt < 4; mt++) {
            unsigned af[4] = { alo[mt].z, ahi[mt].z, alo[mt].w, ahi[mt].w };
            unsigned bf[2];
            bf[0] = b10.x; bf[1] = b11.x; mma_tf32(acc[mt][0], af, bf);
            bf[0] = b10.y; bf[1] = b11.y; mma_tf32(acc[mt][1], af, bf);
            bf[0] = b10.z; bf[1] = b11.z; mma_tf32(acc[mt][2], af, bf);
            bf[0] = b10.w; bf[1] = b11.w; mma_tf32(acc[mt][3], af, bf);
        }
    }

    // Epilogue: bias add (+ optional tf32 rounding) + store
    const int blockM = blockIdx.y * 128;
    const int blockN = blockIdx.x * 128;
    #pragma unroll
    for (int mt = 0; mt < 4; mt++) {
        #pragma unroll
        for (int nt = 0; nt < 4; nt++) {
            int r0 = blockM + wm + mt * 16 + lr;
            int c0 = blockN + wn + nt * 8 + lc * 2;
            float bx = bias[c0], by = bias[c0 + 1];
            float v0x = acc[mt][nt][0] + bx, v0y = acc[mt][nt][1] + by;
            float v1x = acc[mt][nt][2] + bx, v1y = acc[mt][nt][3] + by;
            if (ROUND) {
                v0x = rnd_tf32(v0x); v0y = rnd_tf32(v0y);
                v1x = rnd_tf32(v1x); v1y = rnd_tf32(v1y);
            }
            *(float2*)&C[(size_t)r0 * N + c0]       = make_float2(v0x, v0y);
            *(float2*)&C[(size_t)(r0 + 8) * N + c0] = make_float2(v1x, v1y);
        }
    }
}

// ---------------------------------------------------------------------------
// TF32 MMA causal flash attention, double-buffered cp.async K/V.
// Epilogue writes DIRECTLY into the permuted A-tile layout for GEMM2.
// ---------------------------------------------------------------------------
#define ASM_BYTES 69632

__device__ __forceinline__ void attn_load_kv(uint32_t sb, const float* qkv,
                                             size_t bT, int k0, int h, int buf, int tid)
{
    const uint32_t kbase = sb + buf * 34816;
    #pragma unroll
    for (int i = 0; i < 8; i++) {
        int c = tid + i * 128;
        int key = c >> 4;
        int cw  = c & 15;
        const float* g = qkv + (bT + k0 + key) * N_QKV + CC + h * DD + cw * 4;
        uint32_t d = kbase + key * 272 + cw * 16;
        cp16(d, g);                       // K
        cp16(d + 17408, g + CC);          // V
    }
    cp_commit();
}

__global__ __launch_bounds__(128)
void attn_mma(const float* __restrict__ qkv, float* __restrict__ yp)
{
    extern __shared__ unsigned kvmem[];
    const uint32_t sb = smem_u32(kvmem);

    const int tid  = threadIdx.x;
    const int warp = tid >> 5;
    const int lane = tid & 31;
    const int lr = lane >> 2;
    const int lc = lane & 3;

    const int qb = blockIdx.x;
    const int bh = blockIdx.y;
    const int b  = bh >> 4;
    const int h  = bh & 15;
    const int q0 = qb * 64;
    const size_t bT = (size_t)b * TT;

    const float qscale = 0.125f * 1.4426950408889634f;

    unsigned qa[8][4];
    {
        const int r_lo = q0 + warp * 16 + lr;
        const float* Qlo = qkv + (bT + r_lo) * N_QKV + h * DD;
        const float* Qhi = Qlo + (size_t)8 * N_QKV;
        #pragma unroll
        for (int kk8 = 0; kk8 < 8; kk8++) {
            int d0 = kk8 * 8 + lc;
            qa[kk8][0] = f2tf32(Qlo[d0]     * qscale);
            qa[kk8][1] = f2tf32(Qhi[d0]     * qscale);
            qa[kk8][2] = f2tf32(Qlo[d0 + 4] * qscale);
            qa[kk8][3] = f2tf32(Qhi[d0 + 4] * qscale);
        }
    }

    float O[8][4];
    #pragma unroll
    for (int nt = 0; nt < 8; nt++)
        #pragma unroll
        for (int r = 0; r < 4; r++) O[nt][r] = 0.0f;

    float m_lo = -1e30f, m_hi = -1e30f, l_lo = 0.0f, l_hi = 0.0f;
    const int qrl = warp * 16 + lr;

    attn_load_kv(sb, qkv, bT, 0, h, 0, tid);

    for (int kt = 0; kt <= qb; kt++) {
        const int buf = kt & 1;
        if (kt < qb) {
            attn_load_kv(sb, qkv, bT, (kt + 1) * 64, h, buf ^ 1, tid);
            asm volatile("cp.async.wait_group 1;" ::: "memory");
        } else {
            asm volatile("cp.async.wait_group 0;" ::: "memory");
        }
        __syncthreads();

        unsigned* Kn  = kvmem + buf * 8704;
        unsigned* Vsp = Kn + 4352;
        unsigned* Psp = Kn + warp * 16 * 68;

        float s[8][4];
        #pragma unroll
        for (int nt = 0; nt < 8; nt++)
            #pragma unroll
            for (int r = 0; r < 4; r++) s[nt][r] = 0.0f;

        #pragma unroll
        for (int kk8 = 0; kk8 < 8; kk8++) {
            const int dcol = kk8 * 8 + lc;
            #pragma unroll
            for (int nt = 0; nt < 8; nt++) {
                unsigned bfr[2];
                bfr[0] = Kn[(nt * 8 + lr) * 68 + dcol];
                bfr[1] = Kn[(nt * 8 + lr) * 68 + dcol + 4];
                mma_tf32(s[nt], qa[kk8], bfr);
            }
        }

        if (kt == qb) {
            #pragma unroll
            for (int nt = 0; nt < 8; nt++) {
                int kcol = nt * 8 + 2 * lc;
                if (kcol     > qrl)     s[nt][0] = -1e30f;
                if (kcol + 1 > qrl)     s[nt][1] = -1e30f;
                if (kcol     > qrl + 8) s[nt][2] = -1e30f;
                if (kcol + 1 > qrl + 8) s[nt][3] = -1e30f;
            }
        }

        float rl = -1e30f, rh = -1e30f;
        #pragma unroll
        for (int nt = 0; nt < 8; nt++) {
            rl = fmaxf(rl, fmaxf(s[nt][0], s[nt][1]));
            rh = fmaxf(rh, fmaxf(s[nt][2], s[nt][3]));
        }
        rl = fmaxf(rl, __shfl_xor_sync(0xffffffffu, rl, 1));
        rl = fmaxf(rl, __shfl_xor_sync(0xffffffffu, rl, 2));
        rh = fmaxf(rh, __shfl_xor_sync(0xffffffffu, rh, 1));
        rh = fmaxf(rh, __shfl_xor_sync(0xffffffffu, rh, 2));

        float mnl = fmaxf(m_lo, rl), mnh = fmaxf(m_hi, rh);
        float cl = exp2a(m_lo - mnl), ch = exp2a(m_hi - mnh);
        m_lo = mnl; m_hi = mnh;

        unsigned pb[8][4];
        float suml = 0.0f, sumh = 0.0f;
        #pragma unroll
        for (int nt = 0; nt < 8; nt++) {
            pb[nt][0] = f2tf32(exp2a(s[nt][0] - mnl));
            pb[nt][1] = f2tf32(exp2a(s[nt][1] - mnl));
            pb[nt][2] = f2tf32(exp2a(s[nt][2] - mnh));
            pb[nt][3] = f2tf32(exp2a(s[nt][3] - mnh));
            suml += __uint_as_float(pb[nt][0]) + __uint_as_float(pb[nt][1]);
            sumh += __uint_as_float(pb[nt][2]) + __uint_as_float(pb[nt][3]);
        }
        suml += __shfl_xor_sync(0xffffffffu, suml, 1);
        suml += __shfl_xor_sync(0xffffffffu, suml, 2);
        sumh += __shfl_xor_sync(0xffffffffu, sumh, 1);
        sumh += __shfl_xor_sync(0xffffffffu, sumh, 2);
        l_lo = l_lo * cl + suml;
        l_hi = l_hi * ch + sumh;

        #pragma unroll
        for (int nt = 0; nt < 8; nt++) {
            O[nt][0] *= cl; O[nt][1] *= cl;
            O[nt][2] *= ch; O[nt][3] *= ch;
        }

        __syncthreads();

        #pragma unroll
        for (int nt = 0; nt < 8; nt++) {
            *(uint2*)&Psp[lr * 68 + nt * 8 + 2 * lc]       = make_uint2(pb[nt][0], pb[nt][1]);
            *(uint2*)&Psp[(lr + 8) * 68 + nt * 8 + 2 * lc] = make_uint2(pb[nt][2], pb[nt][3]);
        }
        __syncwarp();

        #pragma unroll
        for (int kk8 = 0; kk8 < 8; kk8++) {
            unsigned pa[4];
            pa[0] = Psp[lr * 68 + kk8 * 8 + lc];
            pa[1] = Psp[(lr + 8) * 68 + kk8 * 8 + lc];
            pa[2] = Psp[lr * 68 + kk8 * 8 + lc + 4];
            pa[3] = Psp[(lr + 8) * 68 + kk8 * 8 + lc + 4];
            #pragma unroll
            for (int nt = 0; nt < 8; nt++) {
                unsigned bfr[2];
                bfr[0] = Vsp[(kk8 * 8 + lc) * 68 + nt * 8 + lr];
                bfr[1] = Vsp[(kk8 * 8 + lc + 4) * 68 + nt * 8 + lr];
                mma_tf32(O[nt], pa, bfr);
            }
        }
        __syncthreads();
    }

    // ---- Epilogue: normalize, round, store in permuted A-tile layout ----
    // Global row gr: tile mb=gr>>7, row=gr&127, s=(row^(row>>2))&3.
    // Column gcol: kb=gcol>>4, k=gcol&15.
    // idx = (mb*64+kb)*2048 + row*16 + (((k&3)^s)<<2) + (k>>2)
    const float il = 1.0f / l_lo;
    const float ih = 1.0f / l_hi;
    {
        const int grL = (int)bT + q0 + qrl;
        const int grH = grL + 8;
        const int mbL = grL >> 7, rowL = grL & 127;
        const int mbH = grH >> 7, rowH = grH & 127;
        const int sL = (rowL ^ (rowL >> 2)) & 3;
        const int sH = (rowH ^ (rowH >> 2)) & 3;
        float* baseL = yp + (size_t)(mbL * 64) * 2048 + rowL * 16;
        float* baseH = yp + (size_t)(mbH * 64) * 2048 + rowH * 16;
        #pragma unroll
        for (int nt = 0; nt < 8; nt++) {
            int c0 = nt * 8 + 2 * lc;         // 0..63 within head
            int gcol = h * DD + c0;
            int kb = gcol >> 4;
            int k0w = gcol & 15;              // k for elem 0; elem 1 is k0w+1
            // element 0 (even k), element 1 (odd k): same k>>2 group? k0w is even.
            int t0 = k0w >> 2, q0w = (k0w & 3);
            int t1 = (k0w + 1) >> 2, q1w = ((k0w + 1) & 3);
            baseL[(size_t)kb * 2048 + ((q0w ^ sL) << 2) + t0] = rnd_tf32(O[nt][0] * il);
            baseL[(size_t)kb * 2048 + ((q1w ^ sL) << 2) + t1] = rnd_tf32(O[nt][1] * il);
            baseH[(size_t)kb * 2048 + ((q0w ^ sH) << 2) + t0] = rnd_tf32(O[nt][2] * ih);
            baseH[(size_t)kb * 2048 + ((q1w ^ sH) << 2) + t1] = rnd_tf32(O[nt][3] * ih);
        }
    }
}

// ---------------------------------------------------------------------------
// Launch
// ---------------------------------------------------------------------------
extern "C" void kernel_launch(void* const* d_in, const int* in_sizes, int n_in,
                              void* d_out, int out_size)
{
    const float* x      = (const float*)d_in[0];
    const float* w_qkv  = (const float*)d_in[1];
    const float* b_qkv  = (const float*)d_in[2];
    const float* w_proj = (const float*)d_in[3];
    const float* b_proj = (const float*)d_in[4];
    float* out = (float*)d_out;

    float *qkv, *xp, *yp, *wqkvp, *wprojp;
    cudaGetSymbolAddress((void**)&qkv,    g_qkv);
    cudaGetSymbolAddress((void**)&xp,     g_xp);
    cudaGetSymbolAddress((void**)&yp,     g_yp);
    cudaGetSymbolAddress((void**)&wqkvp,  g_wqkvp);
    cudaGetSymbolAddress((void**)&wprojp, g_wprojp);

    cudaFuncSetAttribute(gemm_pipe<true>,  cudaFuncAttributeMaxDynamicSharedMemorySize, GSM_BYTES);
    cudaFuncSetAttribute(gemm_pipe<false>, cudaFuncAttributeMaxDynamicSharedMemorySize, GSM_BYTES);
    cudaFuncSetAttribute(attn_mma, cudaFuncAttributeMaxDynamicSharedMemorySize, ASM_BYTES);

    // 0) Permute + round inputs
    {
        int nA = M_ROWS * CC;
        permute_a_kernel<<<(nA + 255) / 256, 256>>>(x, xp, CC, nA);
        int nB1 = CC * N_QKV;
        permute_b_kernel<<<(nB1 + 255) / 256, 256>>>(w_qkv, wqkvp, N_QKV, CC, nB1);
        int nB2 = CC * CC;
        permute_b_kernel<<<(nB2 + 255) / 256, 256>>>(w_proj, wprojp, CC, CC, nB2);
    }

    // 1) QKV projection (epilogue rounds to tf32 for attention consumption)
    gemm_pipe<true><<<dim3(N_QKV / 128, M_ROWS / 128), 256, GSM_BYTES>>>(
        xp, wqkvp, b_qkv, qkv, N_QKV, CC);

    // 2) Causal attention (writes permuted yp directly)
    attn_mma<<<dim3(TT / 64, BB * HH), 128, ASM_BYTES>>>(qkv, yp);

    // 3) Output projection (no rounding on final output)
    gemm_pipe<false><<<dim3(CC / 128, M_ROWS / 128), 256, GSM_BYTES>>>(
        yp, wprojp, b_proj, out, CC, CC);
}

// round 9
// speedup vs baseline: 1.0264x; 1.0264x over previous
#include <cuda_runtime.h>
#include <cuda_bf16.h>
#include <cstdint>

// Problem constants
#define BB 4
#define TT 2048
#define CC 1024
#define HH 16
#define DD 64
#define M_ROWS (BB * TT)          // 8192
#define N_QKV  (3 * CC)           // 3072

// Scratch (device globals — allocation-free)
__device__ float g_qkv[(size_t)M_ROWS * N_QKV];       // [B*T, 3C] (tf32-rounded)
__device__ float g_xp[(size_t)M_ROWS * CC];           // x, permuted A-tiles
__device__ float g_yp[(size_t)M_ROWS * CC];           // attention out, permuted A-tiles
__device__ float g_wqkvp[(size_t)CC * N_QKV];         // w_qkv, permuted B-tiles
__device__ float g_wprojp[(size_t)CC * CC];           // w_proj, permuted B-tiles

// ---------------------------------------------------------------------------
// Helpers
// ---------------------------------------------------------------------------
__device__ __forceinline__ unsigned f2tf32(float x) {
    unsigned r;
    asm("cvt.rna.tf32.f32 %0, %1;" : "=r"(r) : "f"(x));
    return r;
}
__device__ __forceinline__ float rnd_tf32(float x) {
    return __uint_as_float(f2tf32(x));
}
__device__ __forceinline__ float exp2a(float x) {
    float r;
    asm("ex2.approx.ftz.f32 %0, %1;" : "=f"(r) : "f"(x));
    return r;
}
__device__ __forceinline__ void mma_tf32(float* c, const unsigned* a, const unsigned* b) {
    asm volatile(
        "mma.sync.aligned.m16n8k8.row.col.f32.tf32.tf32.f32 "
        "{%0,%1,%2,%3}, {%4,%5,%6,%7}, {%8,%9}, {%0,%1,%2,%3};"
        : "+f"(c[0]), "+f"(c[1]), "+f"(c[2]), "+f"(c[3])
        : "r"(a[0]), "r"(a[1]), "r"(a[2]), "r"(a[3]),
          "r"(b[0]), "r"(b[1]));
}
__device__ __forceinline__ uint32_t smem_u32(const void* p) {
    uint32_t a;
    asm("{ .reg .u64 t; cvta.to.shared.u64 t, %1; cvt.u32.u64 %0, t; }" : "=r"(a) : "l"(p));
    return a;
}
__device__ __forceinline__ void cp16(uint32_t s, const void* g) {
    asm volatile("cp.async.cg.shared.global [%0], [%1], 16;" :: "r"(s), "l"(g));
}
__device__ __forceinline__ void cp_commit() {
    asm volatile("cp.async.commit_group;" ::: "memory");
}

// ---------------------------------------------------------------------------
// Prep: permute A (row-major [M][K] fp32) into GEMM A-tile layout, tf32-rounded.
// ---------------------------------------------------------------------------
__global__ __launch_bounds__(256)
void permute_a_kernel(const float* __restrict__ in, float* __restrict__ out, int K, int nTot)
{
    int idx = blockIdx.x * 256 + threadIdx.x;
    if (idx >= nTot) return;
    const int nk = K >> 4;
    int tile = idx >> 11, w = idx & 2047;
    int mb = tile / nk, kb = tile - mb * nk;
    int row = w >> 4, rem = w & 15;
    int q = rem >> 2, t = rem & 3;
    int s = (row ^ (row >> 2)) & 3;
    int k = (t << 2) | (q ^ s);
    out[idx] = rnd_tf32(in[(size_t)(mb * 128 + row) * K + kb * 16 + k]);
}

// ---------------------------------------------------------------------------
// Prep: permute B (row-major [K][N] fp32) into GEMM B-tile layout, tf32-rounded.
// ---------------------------------------------------------------------------
__global__ __launch_bounds__(256)
void permute_b_kernel(const float* __restrict__ in, float* __restrict__ out, int N, int K, int nTot)
{
    int idx = blockIdx.x * 256 + threadIdx.x;
    if (idx >= nTot) return;
    const int nk = K >> 4;
    int tile = idx >> 11, w = idx & 2047;
    int nb = tile / nk, kb = tile - nb * nk;
    int k = w >> 7, p = w & 127;
    int n = (p & 15) * 8 + (p >> 4);
    out[idx] = rnd_tf32(in[(size_t)(kb * 16 + k) * N + nb * 128 + n]);
}

// ---------------------------------------------------------------------------
// Pipelined TF32 mma.sync GEMM:  C[M,N] = A @ B + bias.
// BK=32 (two kb-blocks per stage), 3-stage cp.async, 128x128 tile, 8 warps.
// smem: A stages (3 x 16384B) at 0; B stages (3 x 16896B) at 49152.
// ---------------------------------------------------------------------------
#define GSM_BYTES 99840

__device__ __forceinline__ void gemm_load_stage32(uint32_t sb, const float* Atile,
                                                  const float* Btile, int st, int kb32, int tid)
{
    #pragma unroll
    for (int half = 0; half < 2; half++) {
        const float* Ab = Atile + (size_t)(2 * kb32 + half) * 2048;
        const float* Bb = Btile + (size_t)(2 * kb32 + half) * 2048;
        const uint32_t as_ = sb + st * 16384 + half * 8192;
        const uint32_t bs_ = sb + 49152 + st * 16896 + half * 8448;
        cp16(as_ + tid * 16, Ab + tid * 4);
        cp16(as_ + (tid + 256) * 16, Ab + (tid + 256) * 4);
        const int c0 = tid, c1 = tid + 256;
        cp16(bs_ + (c0 >> 5) * 528 + (c0 & 31) * 16, Bb + c0 * 4);
        cp16(bs_ + (c1 >> 5) * 528 + (c1 & 31) * 16, Bb + c1 * 4);
    }
    cp_commit();
}

template <bool ROUND>
__global__ __launch_bounds__(256, 2)
void gemm_pipe(const float* __restrict__ Ap, const float* __restrict__ Bp,
               const float* __restrict__ bias, float* __restrict__ C,
               int N, int K)
{
    extern __shared__ char smem[];
    const uint32_t sb = smem_u32(smem);
    const int tid  = threadIdx.x;
    const int warp = tid >> 5;
    const int lane = tid & 31;
    const int lr = lane >> 2;
    const int lc = lane & 3;
    const int wm = (warp >> 2) * 64;
    const int wn = (warp & 3) * 32;
    const int wn8 = wn >> 3;
    const int nk   = K >> 4;    // kb blocks
    const int nk32 = K >> 5;    // BK=32 iterations

    const float* Atile = Ap + (size_t)blockIdx.y * nk * 2048;
    const float* Btile = Bp + (size_t)blockIdx.x * nk * 2048;

    int aRd[4][2];
    #pragma unroll
    for (int mt = 0; mt < 4; mt++) {
        int rm = wm + mt * 16 + lr;
        int r8 = rm + 8;
        aRd[mt][0] = rm * 16 + 4 * (lc ^ ((rm ^ (rm >> 2)) & 3));
        aRd[mt][1] = r8 * 16 + 4 * (lc ^ ((r8 ^ (r8 >> 2)) & 3));
    }
    const int bRd = lr * 16 + wn8;

    float acc[4][4][4];
    #pragma unroll
    for (int i = 0; i < 4; i++)
        #pragma unroll
        for (int j = 0; j < 4; j++)
            #pragma unroll
            for (int r = 0; r < 4; r++) acc[i][j][r] = 0.0f;

    // Prologue: stages 0,1
    gemm_load_stage32(sb, Atile, Btile, 0, 0, tid);
    gemm_load_stage32(sb, Atile, Btile, 1, 1, tid);

    int st = 0;       // consume stage
    for (int i = 0; i < nk32; i++) {
        if (i + 1 < nk32)
            asm volatile("cp.async.wait_group 1;" ::: "memory");
        else
            asm volatile("cp.async.wait_group 0;" ::: "memory");
        __syncthreads();

        if (i + 2 < nk32) {
            int lst = st + 2; if (lst >= 3) lst -= 3;
            gemm_load_stage32(sb, Atile, Btile, lst, i + 2, tid);
        }

        #pragma unroll
        for (int half = 0; half < 2; half++) {
            const unsigned* asb = (const unsigned*)(smem + (size_t)st * 16384 + half * 8192);
            const unsigned* bsb = (const unsigned*)(smem + 49152 + (size_t)st * 16896 + half * 8448);

            uint4 b00 = *(const uint4*)&bsb[(lc)      * 132 + bRd];
            uint4 b01 = *(const uint4*)&bsb[(lc + 4)  * 132 + bRd];
            uint4 b10 = *(const uint4*)&bsb[(lc + 8)  * 132 + bRd];
            uint4 b11 = *(const uint4*)&bsb[(lc + 12) * 132 + bRd];

            #pragma unroll
            for (int mt = 0; mt < 4; mt++) {
                uint4 lo = *(const uint4*)&asb[aRd[mt][0]];
                uint4 hi = *(const uint4*)&asb[aRd[mt][1]];
                unsigned af0[4] = { lo.x, hi.x, lo.y, hi.y };
                unsigned af1[4] = { lo.z, hi.z, lo.w, hi.w };
                unsigned bf[2];
                bf[0] = b00.x; bf[1] = b01.x; mma_tf32(acc[mt][0], af0, bf);
                bf[0] = b00.y; bf[1] = b01.y; mma_tf32(acc[mt][1], af0, bf);
                bf[0] = b00.z; bf[1] = b01.z; mma_tf32(acc[mt][2], af0, bf);
                bf[0] = b00.w; bf[1] = b01.w; mma_tf32(acc[mt][3], af0, bf);
                bf[0] = b10.x; bf[1] = b11.x; mma_tf32(acc[mt][0], af1, bf);
                bf[0] = b10.y; bf[1] = b11.y; mma_tf32(acc[mt][1], af1, bf);
                bf[0] = b10.z; bf[1] = b11.z; mma_tf32(acc[mt][2], af1, bf);
                bf[0] = b10.w; bf[1] = b11.w; mma_tf32(acc[mt][3], af1, bf);
            }
        }
        st = (st + 1 == 3) ? 0 : st + 1;
    }

    // Epilogue: bias add (+ optional tf32 rounding) + store
    const int blockM = blockIdx.y * 128;
    const int blockN = blockIdx.x * 128;
    #pragma unroll
    for (int mt = 0; mt < 4; mt++) {
        #pragma unroll
        for (int nt = 0; nt < 4; nt++) {
            int r0 = blockM + wm + mt * 16 + lr;
            int c0 = blockN + wn + nt * 8 + lc * 2;
            float bx = bias[c0], by = bias[c0 + 1];
            float v0x = acc[mt][nt][0] + bx, v0y = acc[mt][nt][1] + by;
            float v1x = acc[mt][nt][2] + bx, v1y = acc[mt][nt][3] + by;
            if (ROUND) {
                v0x = rnd_tf32(v0x); v0y = rnd_tf32(v0y);
                v1x = rnd_tf32(v1x); v1y = rnd_tf32(v1y);
            }
            *(float2*)&C[(size_t)r0 * N + c0]       = make_float2(v0x, v0y);
            *(float2*)&C[(size_t)(r0 + 8) * N + c0] = make_float2(v1x, v1y);
        }
    }
}

// ---------------------------------------------------------------------------
// TF32 MMA causal flash attention.
// 256 threads, 128 queries/block (8 warps x 16 rows), 64-key tiles,
// double-buffered cp.async K/V, separate P buffer, ONE syncthreads per tile.
// smem words: K/V buf0 @0 (8704), buf1 @8704, P @17408 (8704) -> 104448 B.
// ---------------------------------------------------------------------------
#define ASM_BYTES 104448

__device__ __forceinline__ void attn_load_kv(uint32_t sb, const float* qkv,
                                             size_t bT, int k0, int h, int buf, int tid)
{
    const uint32_t kbase = sb + buf * 34816;
    #pragma unroll
    for (int i = 0; i < 4; i++) {
        int c = tid + i * 256;
        int key = c >> 4;
        int cw  = c & 15;
        const float* g = qkv + (bT + k0 + key) * N_QKV + CC + h * DD + cw * 4;
        uint32_t d = kbase + key * 272 + cw * 16;
        cp16(d, g);                       // K
        cp16(d + 17408, g + CC);          // V
    }
    cp_commit();
}

__global__ __launch_bounds__(256, 2)
void attn_mma(const float* __restrict__ qkv, float* __restrict__ yp)
{
    extern __shared__ unsigned kvmem[];
    const uint32_t sb = smem_u32(kvmem);

    const int tid  = threadIdx.x;
    const int warp = tid >> 5;
    const int lane = tid & 31;
    const int lr = lane >> 2;
    const int lc = lane & 3;

    const int qb = blockIdx.x;
    const int bh = blockIdx.y;
    const int b  = bh >> 4;
    const int h  = bh & 15;
    const int q0 = qb * 128;
    const size_t bT = (size_t)b * TT;

    const float qscale = 0.125f * 1.4426950408889634f;

    // Q fragments (register-resident; warp owns rows q0+16*warp .. +15)
    unsigned qa[8][4];
    {
        const int r_lo = q0 + warp * 16 + lr;
        const float* Qlo = qkv + (bT + r_lo) * N_QKV + h * DD;
        const float* Qhi = Qlo + (size_t)8 * N_QKV;
        #pragma unroll
        for (int kk8 = 0; kk8 < 8; kk8++) {
            int d0 = kk8 * 8 + lc;
            qa[kk8][0] = f2tf32(Qlo[d0]     * qscale);
            qa[kk8][1] = f2tf32(Qhi[d0]     * qscale);
            qa[kk8][2] = f2tf32(Qlo[d0 + 4] * qscale);
            qa[kk8][3] = f2tf32(Qhi[d0 + 4] * qscale);
        }
    }

    float O[8][4];
    #pragma unroll
    for (int nt = 0; nt < 8; nt++)
        #pragma unroll
        for (int r = 0; r < 4; r++) O[nt][r] = 0.0f;

    float m_lo = -1e30f, m_hi = -1e30f, l_lo = 0.0f, l_hi = 0.0f;
    const int ktmax = 2 * qb + 1;      // inclusive last tile

    attn_load_kv(sb, qkv, bT, 0, h, 0, tid);

    for (int kt = 0; kt <= ktmax; kt++) {
        const int buf = kt & 1;
        asm volatile("cp.async.wait_group 0;" ::: "memory");
        __syncthreads();
        if (kt < ktmax)
            attn_load_kv(sb, qkv, bT, (kt + 1) * 64, h, buf ^ 1, tid);

        // base is a multiple of 16: base < 0 => tile fully masked for this warp
        const int base = q0 + warp * 16 - kt * 64;
        if (base >= 0) {
            unsigned* Kn  = kvmem + buf * 8704;
            unsigned* Vsp = Kn + 4352;
            unsigned* Psp = kvmem + 17408 + warp * 1088;

            float s[8][4];
            #pragma unroll
            for (int nt = 0; nt < 8; nt++)
                #pragma unroll
                for (int r = 0; r < 4; r++) s[nt][r] = 0.0f;

            #pragma unroll
            for (int kk8 = 0; kk8 < 8; kk8++) {
                const int dcol = kk8 * 8 + lc;
                #pragma unroll
                for (int nt = 0; nt < 8; nt++) {
                    unsigned bfr[2];
                    bfr[0] = Kn[(nt * 8 + lr) * 68 + dcol];
                    bfr[1] = Kn[(nt * 8 + lr) * 68 + dcol + 4];
                    mma_tf32(s[nt], qa[kk8], bfr);
                }
            }

            if (base < 64) {
                #pragma unroll
                for (int nt = 0; nt < 8; nt++) {
                    int kcol = nt * 8 + 2 * lc;
                    if (kcol     > base + lr)     s[nt][0] = -1e30f;
                    if (kcol + 1 > base + lr)     s[nt][1] = -1e30f;
                    if (kcol     > base + lr + 8) s[nt][2] = -1e30f;
                    if (kcol + 1 > base + lr + 8) s[nt][3] = -1e30f;
                }
            }

            float rl = -1e30f, rh = -1e30f;
            #pragma unroll
            for (int nt = 0; nt < 8; nt++) {
                rl = fmaxf(rl, fmaxf(s[nt][0], s[nt][1]));
                rh = fmaxf(rh, fmaxf(s[nt][2], s[nt][3]));
            }
            rl = fmaxf(rl, __shfl_xor_sync(0xffffffffu, rl, 1));
            rl = fmaxf(rl, __shfl_xor_sync(0xffffffffu, rl, 2));
            rh = fmaxf(rh, __shfl_xor_sync(0xffffffffu, rh, 1));
            rh = fmaxf(rh, __shfl_xor_sync(0xffffffffu, rh, 2));

            float mnl = fmaxf(m_lo, rl), mnh = fmaxf(m_hi, rh);
            float cl = exp2a(m_lo - mnl), ch = exp2a(m_hi - mnh);
            m_lo = mnl; m_hi = mnh;

            unsigned pb[8][4];
            float suml = 0.0f, sumh = 0.0f;
            #pragma unroll
            for (int nt = 0; nt < 8; nt++) {
                pb[nt][0] = f2tf32(exp2a(s[nt][0] - mnl));
                pb[nt][1] = f2tf32(exp2a(s[nt][1] - mnl));
                pb[nt][2] = f2tf32(exp2a(s[nt][2] - mnh));
                pb[nt][3] = f2tf32(exp2a(s[nt][3] - mnh));
                suml += __uint_as_float(pb[nt][0]) + __uint_as_float(pb[nt][1]);
                sumh += __uint_as_float(pb[nt][2]) + __uint_as_float(pb[nt][3]);
            }
            suml += __shfl_xor_sync(0xffffffffu, suml, 1);
            suml += __shfl_xor_sync(0xffffffffu, suml, 2);
            sumh += __shfl_xor_sync(0xffffffffu, sumh, 1);
            sumh += __shfl_xor_sync(0xffffffffu, sumh, 2);
            l_lo = l_lo * cl + suml;
            l_hi = l_hi * ch + sumh;

            #pragma unroll
            for (int nt = 0; nt < 8; nt++) {
                O[nt][0] *= cl; O[nt][1] *= cl;
                O[nt][2] *= ch; O[nt][3] *= ch;
            }

            // P round-trip through the warp's private region (no CTA barrier)
            #pragma unroll
            for (int nt = 0; nt < 8; nt++) {
                *(uint2*)&Psp[lr * 68 + nt * 8 + 2 * lc]       = make_uint2(pb[nt][0], pb[nt][1]);
                *(uint2*)&Psp[(lr + 8) * 68 + nt * 8 + 2 * lc] = make_uint2(pb[nt][2], pb[nt][3]);
            }
            __syncwarp();

            #pragma unroll
            for (int kk8 = 0; kk8 < 8; kk8++) {
                unsigned pa[4];
                pa[0] = Psp[lr * 68 + kk8 * 8 + lc];
                pa[1] = Psp[(lr + 8) * 68 + kk8 * 8 + lc];
                pa[2] = Psp[lr * 68 + kk8 * 8 + lc + 4];
                pa[3] = Psp[(lr + 8) * 68 + kk8 * 8 + lc + 4];
                #pragma unroll
                for (int nt = 0; nt < 8; nt++) {
                    unsigned bfr[2];
                    bfr[0] = Vsp[(kk8 * 8 + lc) * 68 + nt * 8 + lr];
                    bfr[1] = Vsp[(kk8 * 8 + lc + 4) * 68 + nt * 8 + lr];
                    mma_tf32(O[nt], pa, bfr);
                }
            }
        }
    }

    // ---- Epilogue: normalize, round, store in permuted A-tile layout ----
    const float il = 1.0f / l_lo;
    const float ih = 1.0f / l_hi;
    {
        const int grL = (int)bT + q0 + warp * 16 + lr;
        const int grH = grL + 8;
        const int mbL = grL >> 7, rowL = grL & 127;
        const int mbH = grH >> 7, rowH = grH & 127;
        const int sL = (rowL ^ (rowL >> 2)) & 3;
        const int sH = (rowH ^ (rowH >> 2)) & 3;
        float* baseL = yp + (size_t)(mbL * 64) * 2048 + rowL * 16;
        float* baseH = yp + (size_t)(mbH * 64) * 2048 + rowH * 16;
        #pragma unroll
        for (int nt = 0; nt < 8; nt++) {
            int c0 = nt * 8 + 2 * lc;
            int gcol = h * DD + c0;
            int kb = gcol >> 4;
            int k0w = gcol & 15;
            int t0 = k0w >> 2, q0w = (k0w & 3);
            int t1 = (k0w + 1) >> 2, q1w = ((k0w + 1) & 3);
            baseL[(size_t)kb * 2048 + ((q0w ^ sL) << 2) + t0] = rnd_tf32(O[nt][0] * il);
            baseL[(size_t)kb * 2048 + ((q1w ^ sL) << 2) + t1] = rnd_tf32(O[nt][1] * il);
            baseH[(size_t)kb * 2048 + ((q0w ^ sH) << 2) + t0] = rnd_tf32(O[nt][2] * ih);
            baseH[(size_t)kb * 2048 + ((q1w ^ sH) << 2) + t1] = rnd_tf32(O[nt][3] * ih);
        }
    }
}

// ---------------------------------------------------------------------------
// Launch
// ---------------------------------------------------------------------------
extern "C" void kernel_launch(void* const* d_in, const int* in_sizes, int n_in,
                              void* d_out, int out_size)
{
    const float* x      = (const float*)d_in[0];
    const float* w_qkv  = (const float*)d_in[1];
    const float* b_qkv  = (const float*)d_in[2];
    const float* w_proj = (const float*)d_in[3];
    const float* b_proj = (const float*)d_in[4];
    float* out = (float*)d_out;

    float *qkv, *xp, *yp, *wqkvp, *wprojp;
    cudaGetSymbolAddress((void**)&qkv,    g_qkv);
    cudaGetSymbolAddress((void**)&xp,     g_xp);
    cudaGetSymbolAddress((void**)&yp,     g_yp);
    cudaGetSymbolAddress((void**)&wqkvp,  g_wqkvp);
    cudaGetSymbolAddress((void**)&wprojp, g_wprojp);

    cudaFuncSetAttribute(gemm_pipe<true>,  cudaFuncAttributeMaxDynamicSharedMemorySize, GSM_BYTES);
    cudaFuncSetAttribute(gemm_pipe<false>, cudaFuncAttributeMaxDynamicSharedMemorySize, GSM_BYTES);
    cudaFuncSetAttribute(attn_mma, cudaFuncAttributeMaxDynamicSharedMemorySize, ASM_BYTES);

    // 0) Permute + round inputs
    {
        int nA = M_ROWS * CC;
        permute_a_kernel<<<(nA + 255) / 256, 256>>>(x, xp, CC, nA);
        int nB1 = CC * N_QKV;
        permute_b_kernel<<<(nB1 + 255) / 256, 256>>>(w_qkv, wqkvp, N_QKV, CC, nB1);
        int nB2 = CC * CC;
        permute_b_kernel<<<(nB2 + 255) / 256, 256>>>(w_proj, wprojp, CC, CC, nB2);
    }

    // 1) QKV projection (epilogue rounds to tf32 for attention consumption)
    gemm_pipe<true><<<dim3(N_QKV / 128, M_ROWS / 128), 256, GSM_BYTES>>>(
        xp, wqkvp, b_qkv, qkv, N_QKV, CC);

    // 2) Causal attention (writes permuted yp directly)
    attn_mma<<<dim3(TT / 128, BB * HH), 256, ASM_BYTES>>>(qkv, yp);

    // 3) Output projection (no rounding on final output)
    gemm_pipe<false><<<dim3(CC / 128, M_ROWS / 128), 256, GSM_BYTES>>>(
        yp, wprojp, b_proj, out, CC, CC);
}